// round 1
// baseline (speedup 1.0000x reference)
#include <cuda_runtime.h>
#include <cuda_bf16.h>
#include <cstddef>

// Problem constants
constexpr int B_   = 8;
constexpr int N_   = 2048;
constexpr int D_   = 1024;
constexpr int H_   = 2048;
constexpr int MTOT = B_ * N_;     // 16384 rows total
constexpr int SEGLEN = 512;

// Scratch (device globals; no allocations allowed)
__device__ float g_s1[(size_t)MTOT * H_];  // x @ w1  (gate, pre-silu)
__device__ float g_h [(size_t)MTOT * H_];  // silu(gate) * (x @ w3)

// ---------------------------------------------------------------------------
// Tiled SGEMM: C[M,N] = A[M,K] @ W[seg][K,N], row-major everywhere.
// BM=BN=128, BK=8, 256 threads, 8x8 register tile per thread.
// epi == 0 : C = acc
// epi == 1 : C = silu(Prev) * acc     (Prev same shape as C)
// Segment chosen per 128-row tile: rows within a tile share a segment
// because 128 | 512 and 512 | 2048.
// ---------------------------------------------------------------------------
#define BM 128
#define BN 128
#define BK 8
#define TM 8
#define TN 8

__global__ __launch_bounds__(256, 2)
void sgemm_seg_kernel(const float* __restrict__ A,
                      const float* __restrict__ W,     // [4, K, N]
                      const float* __restrict__ Prev,  // nullable
                      float* __restrict__ C,
                      int N, int K, int epi)
{
    const int bx = blockIdx.x;           // tile col
    const int by = blockIdx.y;           // tile row
    const int seg = ((by * BM) % N_) / SEGLEN;
    const float* Bmat = W + (size_t)seg * K * N;

    __shared__ float As[BK][BM];
    __shared__ float Bs[BK][BN];

    const int tid  = threadIdx.x;
    const int tcol = tid % (BN / TN);    // 0..15
    const int trow = tid / (BN / TN);    // 0..15

    // A tile load mapping: 128 rows x 8 cols, one float4 per thread
    const int aRow = tid >> 1;           // 0..127
    const int aCol = (tid & 1) * 4;      // 0 or 4
    // B tile load mapping: 8 rows x 128 cols, one float4 per thread
    const int bRow = tid >> 5;           // 0..7
    const int bCol = (tid & 31) * 4;     // 0..124

    const float* Aptr = A + (size_t)(by * BM) * K;

    float acc[TM][TN];
    #pragma unroll
    for (int i = 0; i < TM; ++i)
        #pragma unroll
        for (int j = 0; j < TN; ++j) acc[i][j] = 0.0f;

    for (int k0 = 0; k0 < K; k0 += BK) {
        float4 a4 = *(const float4*)(Aptr + (size_t)aRow * K + k0 + aCol);
        As[aCol + 0][aRow] = a4.x;
        As[aCol + 1][aRow] = a4.y;
        As[aCol + 2][aRow] = a4.z;
        As[aCol + 3][aRow] = a4.w;

        float4 b4 = *(const float4*)(Bmat + (size_t)(k0 + bRow) * N + bx * BN + bCol);
        *(float4*)(&Bs[bRow][bCol]) = b4;

        __syncthreads();

        #pragma unroll
        for (int k = 0; k < BK; ++k) {
            float ra[TM], rb[TN];
            #pragma unroll
            for (int i = 0; i < TM; ++i) ra[i] = As[k][trow * TM + i];
            #pragma unroll
            for (int j = 0; j < TN; ++j) rb[j] = Bs[k][tcol * TN + j];
            #pragma unroll
            for (int i = 0; i < TM; ++i)
                #pragma unroll
                for (int j = 0; j < TN; ++j)
                    acc[i][j] = fmaf(ra[i], rb[j], acc[i][j]);
        }
        __syncthreads();
    }

    // Epilogue
    #pragma unroll
    for (int i = 0; i < TM; ++i) {
        const int r = by * BM + trow * TM + i;
        #pragma unroll
        for (int j = 0; j < TN; j += 4) {
            const int c = bx * BN + tcol * TN + j;
            float4 v = make_float4(acc[i][j], acc[i][j + 1], acc[i][j + 2], acc[i][j + 3]);
            if (epi == 1) {
                float4 p = *(const float4*)(Prev + (size_t)r * N + c);
                v.x *= p.x * (1.0f / (1.0f + __expf(-p.x)));
                v.y *= p.y * (1.0f / (1.0f + __expf(-p.y)));
                v.z *= p.z * (1.0f / (1.0f + __expf(-p.z)));
                v.w *= p.w * (1.0f / (1.0f + __expf(-p.w)));
            }
            *(float4*)(C + (size_t)r * N + c) = v;
        }
    }
}

extern "C" void kernel_launch(void* const* d_in, const int* in_sizes, int n_in,
                              void* d_out, int out_size)
{
    const float* x  = (const float*)d_in[0];   // [B, N, D]
    const float* w1 = (const float*)d_in[1];   // [4, D, H]
    const float* w3 = (const float*)d_in[2];   // [4, D, H]
    const float* w2 = (const float*)d_in[3];   // [4, H, D]
    float* out = (float*)d_out;                // [B, N, D]

    float *s1, *h;
    cudaGetSymbolAddress((void**)&s1, g_s1);
    cudaGetSymbolAddress((void**)&h,  g_h);

    dim3 block(256);
    dim3 g1(H_ / BN, MTOT / BM);   // 16 x 128
    dim3 g2(D_ / BN, MTOT / BM);   //  8 x 128

    // s1 = x @ w1[seg]
    sgemm_seg_kernel<<<g1, block>>>(x, w1, nullptr, s1, H_, D_, 0);
    // h = silu(s1) * (x @ w3[seg])
    sgemm_seg_kernel<<<g1, block>>>(x, w3, s1, h, H_, D_, 1);
    // out = h @ w2[seg]
    sgemm_seg_kernel<<<g2, block>>>(h, w2, nullptr, out, D_, H_, 0);
}

// round 3
// speedup vs baseline: 9.8539x; 9.8539x over previous
#include <cuda_runtime.h>
#include <cuda_fp16.h>
#include <cstdint>
#include <cstddef>

// ---------------------------------------------------------------------------
// Problem constants
// ---------------------------------------------------------------------------
constexpr int B_ = 8, N_ = 2048, D_ = 1024, H_ = 2048;
constexpr int MTOT = B_ * N_;      // 16384
constexpr int SEGLEN = 512;

// Scratch (device globals; allocations forbidden)
__device__ __half g_xh [(size_t)MTOT * D_];      // x  as fp16
__device__ __half g_w1h[(size_t)4 * D_ * H_];    // w1 as fp16
__device__ __half g_w3h[(size_t)4 * D_ * H_];
__device__ __half g_w2h[(size_t)4 * H_ * D_];
__device__ __half g_h  [(size_t)MTOT * H_];      // silu(xW1)*(xW3) as fp16

// ---------------------------------------------------------------------------
// Helpers
// ---------------------------------------------------------------------------
__device__ __forceinline__ uint32_t smem_u32(const void* p) {
    uint32_t a;
    asm("{ .reg .u64 t; cvta.to.shared.u64 t, %1; cvt.u32.u64 %0, t; }"
        : "=r"(a) : "l"(p));
    return a;
}

#define CP_ASYNC16(dst, src) \
    asm volatile("cp.async.cg.shared.global [%0], [%1], 16;" :: "r"(dst), "l"(src))
#define CP_COMMIT() asm volatile("cp.async.commit_group;")
#define CP_WAIT1()  asm volatile("cp.async.wait_group 1;")

#define LDSM_X4(r0, r1, r2, r3, addr) \
    asm volatile("ldmatrix.sync.aligned.m8n8.x4.shared.b16 {%0,%1,%2,%3}, [%4];" \
                 : "=r"(r0), "=r"(r1), "=r"(r2), "=r"(r3) : "r"(addr))
#define LDSM_X4_T(r0, r1, r2, r3, addr) \
    asm volatile("ldmatrix.sync.aligned.m8n8.x4.trans.shared.b16 {%0,%1,%2,%3}, [%4];" \
                 : "=r"(r0), "=r"(r1), "=r"(r2), "=r"(r3) : "r"(addr))

#define MMA_16816(d, a, b0, b1) \
    asm volatile( \
        "mma.sync.aligned.m16n8k16.row.col.f32.f16.f16.f32 " \
        "{%0,%1,%2,%3}, {%4,%5,%6,%7}, {%8,%9}, {%0,%1,%2,%3};" \
        : "+f"((d)[0]), "+f"((d)[1]), "+f"((d)[2]), "+f"((d)[3]) \
        : "r"((a)[0]), "r"((a)[1]), "r"((a)[2]), "r"((a)[3]), \
          "r"(b0), "r"(b1))

// ---------------------------------------------------------------------------
// fp32 -> fp16 prepass (RN)
// ---------------------------------------------------------------------------
__global__ void f2h_kernel(const float* __restrict__ s, __half* __restrict__ d,
                           int n) {
    int i = (blockIdx.x * blockDim.x + threadIdx.x) * 4;
    if (i < n) {
        float4 v = *(const float4*)(s + i);
        __half2 h0 = __floats2half2_rn(v.x, v.y);
        __half2 h1 = __floats2half2_rn(v.z, v.w);
        uint2 r;
        r.x = *(const uint32_t*)&h0;
        r.y = *(const uint32_t*)&h1;
        *(uint2*)(d + i) = r;
    }
}

// ---------------------------------------------------------------------------
// Fused GEMM1: h = silu(x @ w1[seg]) * (x @ w3[seg])
// Tile: 128(M) x 64(N per weight), BK=64 halves, 3-stage cp.async pipeline.
// 8 warps = 4(M) x 2(N); warp subtile 32x32 per weight.
// ---------------------------------------------------------------------------
__global__ void __launch_bounds__(256, 2)
ffn_fused_kernel(const __half* __restrict__ X,
                 const __half* __restrict__ W1,
                 const __half* __restrict__ W3,
                 __half* __restrict__ Hout)
{
    constexpr int STAGE_B = 32768;           // A 16KB + B1 8KB + B2 8KB
    constexpr int NK = D_ / 64;              // 16 k-chunks

    extern __shared__ __align__(1024) char smem[];
    const uint32_t sbase = smem_u32(smem);

    const int tid = threadIdx.x, lane = tid & 31, wid = tid >> 5;
    const int wm = wid >> 1, wn = wid & 1;
    const int m0 = blockIdx.y * 128, n0 = blockIdx.x * 64;
    const int seg = (m0 % N_) / SEGLEN;

    const __half* gW1 = W1 + (size_t)seg * D_ * H_;
    const __half* gW3 = W3 + (size_t)seg * D_ * H_;

    // ---- producer: 2048 x 16B chunks per stage, 8 per thread --------------
    auto load_stage = [&](int kt, int slot) {
        const uint32_t st = sbase + slot * STAGE_B;
        #pragma unroll
        for (int j = 0; j < 8; ++j) {
            const int id = tid + j * 256;
            const __half* src;
            uint32_t dst;
            if (id < 1024) {                       // A: x tile [128][64]
                const int r = id >> 3, c = id & 7;
                src = X + (size_t)(m0 + r) * D_ + kt * 64 + c * 8;
                dst = st + r * 128 + ((c ^ (r & 7)) << 4);
            } else {                               // B: weights [64][64] each
                const int id2 = id - 1024;
                const int w = id2 >> 9, k = (id2 >> 3) & 63, c = id2 & 7;
                const __half* wb = w ? gW3 : gW1;
                src = wb + (size_t)(kt * 64 + k) * H_ + n0 + c * 8;
                dst = st + 16384 + w * 8192 + k * 128 + ((c ^ (k & 7)) << 4);
            }
            CP_ASYNC16(dst, src);
        }
        CP_COMMIT();
    };

    // ---- ldmatrix lane geometry -------------------------------------------
    const int lrow = ((lane >> 3) & 1) * 8 + (lane & 7);   // 0..15
    const int hi = lane >> 4;                              // 0/1
    const int sw = lrow & 7;

    float acc[2][2][4][4];
    #pragma unroll
    for (int w = 0; w < 2; ++w)
        #pragma unroll
        for (int mf = 0; mf < 2; ++mf)
            #pragma unroll
            for (int nf = 0; nf < 4; ++nf)
                #pragma unroll
                for (int e = 0; e < 4; ++e) acc[w][mf][nf][e] = 0.0f;

    load_stage(0, 0);
    load_stage(1, 1);

    for (int kt = 0; kt < NK; ++kt) {
        CP_WAIT1();
        __syncthreads();
        if (kt + 2 < NK) load_stage(kt + 2, (kt + 2) % 3);
        else CP_COMMIT();

        const uint32_t stA = sbase + (kt % 3) * STAGE_B;
        const uint32_t stB = stA + 16384;

        #pragma unroll
        for (int kk = 0; kk < 4; ++kk) {
            uint32_t a[2][4];
            #pragma unroll
            for (int mf = 0; mf < 2; ++mf) {
                const int r = wm * 32 + mf * 16 + lrow;
                const uint32_t ad =
                    stA + r * 128 + (((kk * 2 + hi) ^ sw) << 4);
                LDSM_X4(a[mf][0], a[mf][1], a[mf][2], a[mf][3], ad);
            }
            uint32_t b[2][2][4];
            #pragma unroll
            for (int w = 0; w < 2; ++w)
                #pragma unroll
                for (int j = 0; j < 2; ++j) {
                    const int krow = kk * 16 + lrow;
                    const int nchunk = wn * 4 + j * 2 + hi;
                    const uint32_t bd = stB + w * 8192 + krow * 128 +
                                        ((nchunk ^ sw) << 4);
                    LDSM_X4_T(b[w][j][0], b[w][j][1], b[w][j][2], b[w][j][3], bd);
                }
            #pragma unroll
            for (int w = 0; w < 2; ++w)
                #pragma unroll
                for (int mf = 0; mf < 2; ++mf)
                    #pragma unroll
                    for (int nf = 0; nf < 4; ++nf)
                        MMA_16816(acc[w][mf][nf], a[mf],
                                  b[w][nf >> 1][(nf & 1) * 2],
                                  b[w][nf >> 1][(nf & 1) * 2 + 1]);
        }
    }

    // ---- epilogue: silu(acc1) * acc3 -> fp16 h ----------------------------
    #pragma unroll
    for (int mf = 0; mf < 2; ++mf)
        #pragma unroll
        for (int nf = 0; nf < 4; ++nf)
            #pragma unroll
            for (int ep = 0; ep < 2; ++ep) {
                const int r = m0 + wm * 32 + mf * 16 + (lane >> 2) + ep * 8;
                const int c = n0 + wn * 32 + nf * 8 + (lane & 3) * 2;
                const float g0 = acc[0][mf][nf][ep * 2 + 0];
                const float g1 = acc[0][mf][nf][ep * 2 + 1];
                const float u0 = acc[1][mf][nf][ep * 2 + 0];
                const float u1 = acc[1][mf][nf][ep * 2 + 1];
                const float h0 = g0 * (1.0f / (1.0f + __expf(-g0))) * u0;
                const float h1 = g1 * (1.0f / (1.0f + __expf(-g1))) * u1;
                __half2 hv = __floats2half2_rn(h0, h1);
                *(__half2*)(Hout + (size_t)r * H_ + c) = hv;
            }
}

// ---------------------------------------------------------------------------
// GEMM2: out = h @ w2[seg]   (fp32 output)
// Tile: 128(M) x 128(N), BK=64 halves, 3-stage pipeline.
// 8 warps = 2(M) x 4(N); warp subtile 64x32.
// ---------------------------------------------------------------------------
__global__ void __launch_bounds__(256, 2)
gemm2_kernel(const __half* __restrict__ Hin,
             const __half* __restrict__ W2,
             float* __restrict__ Out)
{
    constexpr int STAGE_B = 32768;           // A 16KB + B 16KB
    constexpr int NK = H_ / 64;              // 32 k-chunks

    extern __shared__ __align__(1024) char smem[];
    const uint32_t sbase = smem_u32(smem);

    const int tid = threadIdx.x, lane = tid & 31, wid = tid >> 5;
    const int wm = wid >> 2, wn = wid & 3;
    const int m0 = blockIdx.y * 128, n0 = blockIdx.x * 128;
    const int seg = (m0 % N_) / SEGLEN;

    const __half* gW2 = W2 + (size_t)seg * H_ * D_;

    auto load_stage = [&](int kt, int slot) {
        const uint32_t st = sbase + slot * STAGE_B;
        #pragma unroll
        for (int j = 0; j < 8; ++j) {
            const int id = tid + j * 256;
            const __half* src;
            uint32_t dst;
            if (id < 1024) {                       // A: h tile [128][64]
                const int r = id >> 3, c = id & 7;
                src = Hin + (size_t)(m0 + r) * H_ + kt * 64 + c * 8;
                dst = st + r * 128 + ((c ^ (r & 7)) << 4);
            } else {                               // B: w2 tile [64][128]
                const int id2 = id - 1024;
                const int k = id2 >> 4, c = id2 & 15;
                src = gW2 + (size_t)(kt * 64 + k) * D_ + n0 + c * 8;
                dst = st + 16384 + k * 256 + ((c ^ (k & 7)) << 4);
            }
            CP_ASYNC16(dst, src);
        }
        CP_COMMIT();
    };

    const int lrow = ((lane >> 3) & 1) * 8 + (lane & 7);
    const int hi = lane >> 4;
    const int sw = lrow & 7;

    float acc[4][4][4];
    #pragma unroll
    for (int mf = 0; mf < 4; ++mf)
        #pragma unroll
        for (int nf = 0; nf < 4; ++nf)
            #pragma unroll
            for (int e = 0; e < 4; ++e) acc[mf][nf][e] = 0.0f;

    load_stage(0, 0);
    load_stage(1, 1);

    for (int kt = 0; kt < NK; ++kt) {
        CP_WAIT1();
        __syncthreads();
        if (kt + 2 < NK) load_stage(kt + 2, (kt + 2) % 3);
        else CP_COMMIT();

        const uint32_t stA = sbase + (kt % 3) * STAGE_B;
        const uint32_t stB = stA + 16384;

        #pragma unroll
        for (int kk = 0; kk < 4; ++kk) {
            uint32_t a[4][4];
            #pragma unroll
            for (int mf = 0; mf < 4; ++mf) {
                const int r = wm * 64 + mf * 16 + lrow;
                const uint32_t ad =
                    stA + r * 128 + (((kk * 2 + hi) ^ sw) << 4);
                LDSM_X4(a[mf][0], a[mf][1], a[mf][2], a[mf][3], ad);
            }
            uint32_t b[2][4];
            #pragma unroll
            for (int j = 0; j < 2; ++j) {
                const int krow = kk * 16 + lrow;
                const int nchunk = wn * 4 + j * 2 + hi;
                const uint32_t bd = stB + krow * 256 + ((nchunk ^ sw) << 4);
                LDSM_X4_T(b[j][0], b[j][1], b[j][2], b[j][3], bd);
            }
            #pragma unroll
            for (int mf = 0; mf < 4; ++mf)
                #pragma unroll
                for (int nf = 0; nf < 4; ++nf)
                    MMA_16816(acc[mf][nf], a[mf],
                              b[nf >> 1][(nf & 1) * 2],
                              b[nf >> 1][(nf & 1) * 2 + 1]);
        }
    }

    #pragma unroll
    for (int mf = 0; mf < 4; ++mf)
        #pragma unroll
        for (int nf = 0; nf < 4; ++nf)
            #pragma unroll
            for (int ep = 0; ep < 2; ++ep) {
                const int r = m0 + wm * 64 + mf * 16 + (lane >> 2) + ep * 8;
                const int c = n0 + wn * 32 + nf * 8 + (lane & 3) * 2;
                float2 v = make_float2(acc[mf][nf][ep * 2 + 0],
                                       acc[mf][nf][ep * 2 + 1]);
                *(float2*)(Out + (size_t)r * D_ + c) = v;
            }
}

// ---------------------------------------------------------------------------
extern "C" void kernel_launch(void* const* d_in, const int* in_sizes, int n_in,
                              void* d_out, int out_size)
{
    const float* x  = (const float*)d_in[0];   // [8,2048,1024]
    const float* w1 = (const float*)d_in[1];   // [4,1024,2048]
    const float* w3 = (const float*)d_in[2];   // [4,1024,2048]
    const float* w2 = (const float*)d_in[3];   // [4,2048,1024]
    float* out = (float*)d_out;                // [8,2048,1024]

    __half *xh, *w1h, *w3h, *w2h, *h;
    cudaGetSymbolAddress((void**)&xh,  g_xh);
    cudaGetSymbolAddress((void**)&w1h, g_w1h);
    cudaGetSymbolAddress((void**)&w3h, g_w3h);
    cudaGetSymbolAddress((void**)&w2h, g_w2h);
    cudaGetSymbolAddress((void**)&h,   g_h);

    constexpr int SMEM = 3 * 32768;   // 96 KB
    cudaFuncSetAttribute(ffn_fused_kernel,
                         cudaFuncAttributeMaxDynamicSharedMemorySize, SMEM);
    cudaFuncSetAttribute(gemm2_kernel,
                         cudaFuncAttributeMaxDynamicSharedMemorySize, SMEM);

    // fp32 -> fp16 prepass
    const int nx = MTOT * D_;           // 16.8M
    const int nw = 4 * D_ * H_;         // 8.4M
    f2h_kernel<<<(nx / 4 + 255) / 256, 256>>>(x,  xh,  nx);
    f2h_kernel<<<(nw / 4 + 255) / 256, 256>>>(w1, w1h, nw);
    f2h_kernel<<<(nw / 4 + 255) / 256, 256>>>(w3, w3h, nw);
    f2h_kernel<<<(nw / 4 + 255) / 256, 256>>>(w2, w2h, nw);

    // h = silu(x @ w1[seg]) * (x @ w3[seg])
    ffn_fused_kernel<<<dim3(H_ / 64, MTOT / 128), 256, SMEM>>>(xh, w1h, w3h, h);
    // out = h @ w2[seg]
    gemm2_kernel<<<dim3(D_ / 128, MTOT / 128), 256, SMEM>>>(h, w2h, out);
}